// round 8
// baseline (speedup 1.0000x reference)
#include <cuda_runtime.h>
#include <cuda_bf16.h>

// out[b, 1+d, p] = x[b, c, hx(p)*16+pi, hy(p)*16+pj] + pos[1+d, p]
//   where d = c*256 + pi*16 + pj, (hx,hy) = hilbert_d2xy(32, p)
// out[b, 0, e]   = cls[e] + pos[0, e]
//
// R5 smem-free register transpose + 4-batch pos amortization: each CTA keeps
// its 16-float pos tile in registers and processes 4 batches, with x loads
// double-buffered across batches (v/u) so MLP-4 never drains. Every STG.128
// writes a full 128B line per 8-lane group.

__global__ __launch_bounds__(256) void hilbert_main_kernel(
    const float* __restrict__ x,
    const float* __restrict__ cls,
    const float* __restrict__ pos,
    float* __restrict__ out)
{
    const int tid = threadIdx.x;
    const int w   = tid >> 5;          // warp 0..7  -> d-quads 4w..4w+3
    const int l   = tid & 31;

    const int ptile = blockIdx.x;      // 0..31
    const int dtile = blockIdx.y;      // 0..7
    const int zb    = blockIdx.z;      // 0..15 -> batches 4zb..4zb+3

    const int c   = dtile >> 1;        // channel
    const int pi0 = (dtile & 1) * 8;   // starting patch row within channel
    const int p0  = ptile * 32;
    const int d0  = dtile * 128;
    const int b0  = zb * 4;

    // Per-lane Hilbert base for patch p0+l, batch-independent part
    int pbc;
    {
        int t = p0 + l;
        int hx = 0, hy = 0;
        #pragma unroll
        for (int s = 1; s < 32; s <<= 1) {
            int rx = 1 & (t >> 1);
            int ry = 1 & (t ^ rx);
            if (ry == 0) {
                if (rx == 1) { hx = s - 1 - hx; hy = s - 1 - hy; }
                int tmp = hx; hx = hy; hy = tmp;
            }
            hx += s * rx;
            hy += s * ry;
            t >>= 2;
        }
        pbc = (c * 512 + hx * 16 + pi0) * 512 + hy * 16;
    }

    const int q = l & 7;               // p-quad: patches 4q..4q+3
    const int s = l >> 3;              // sub-row selector
    const int srcoff = w * 512 + s * 4;

    const int a0 = __shfl_sync(0xffffffffu, pbc, 4 * q + 0) + srcoff + b0 * 1048576;
    const int a1 = __shfl_sync(0xffffffffu, pbc, 4 * q + 1) + srcoff + b0 * 1048576;
    const int a2 = __shfl_sync(0xffffffffu, pbc, 4 * q + 2) + srcoff + b0 * 1048576;
    const int a3 = __shfl_sync(0xffffffffu, pbc, 4 * q + 3) + srcoff + b0 * 1048576;

    // Output rows 1 + d0 + 16w + 4s + j, cols p0 + 4q .. +3
    const int prow  = (1 + d0 + 16 * w + 4 * s) * 1024 + (p0 + 4 * q);
    const int outb0 = b0 * (1025 * 1024) + prow;

    // pos tile: loaded ONCE, reused for 4 batches
    const float4 pe0 = *reinterpret_cast<const float4*>(pos + prow);
    const float4 pe1 = *reinterpret_cast<const float4*>(pos + prow + 1024);
    const float4 pe2 = *reinterpret_cast<const float4*>(pos + prow + 2048);
    const float4 pe3 = *reinterpret_cast<const float4*>(pos + prow + 3072);

    // Fused row0 for all 4 batches: out[b, 0, :] = cls + pos[0, :]
    if (ptile == 0 && dtile == 0) {
        float4 cv = *reinterpret_cast<const float4*>(cls + tid * 4);
        float4 pv = *reinterpret_cast<const float4*>(pos + tid * 4);
        cv.x += pv.x; cv.y += pv.y; cv.z += pv.z; cv.w += pv.w;
        #pragma unroll
        for (int i = 0; i < 4; i++)
            *reinterpret_cast<float4*>(out + (b0 + i) * (1025 * 1024) + tid * 4) = cv;
    }

#define EPILOGUE(V0, V1, V2, V3, OB)                                              \
    do {                                                                          \
        float4 r;                                                                 \
        r = make_float4(V0.x + pe0.x, V1.x + pe0.y, V2.x + pe0.z, V3.x + pe0.w);  \
        __stcs(reinterpret_cast<float4*>(out + (OB)), r);                         \
        r = make_float4(V0.y + pe1.x, V1.y + pe1.y, V2.y + pe1.z, V3.y + pe1.w);  \
        __stcs(reinterpret_cast<float4*>(out + (OB) + 1024), r);                  \
        r = make_float4(V0.z + pe2.x, V1.z + pe2.y, V2.z + pe2.z, V3.z + pe2.w);  \
        __stcs(reinterpret_cast<float4*>(out + (OB) + 2048), r);                  \
        r = make_float4(V0.w + pe3.x, V1.w + pe3.y, V2.w + pe3.z, V3.w + pe3.w);  \
        __stcs(reinterpret_cast<float4*>(out + (OB) + 3072), r);                  \
    } while (0)

#define LOADX(V0, V1, V2, V3, XO)                                                 \
    do {                                                                          \
        V0 = *reinterpret_cast<const float4*>(x + a0 + (XO));                     \
        V1 = *reinterpret_cast<const float4*>(x + a1 + (XO));                     \
        V2 = *reinterpret_cast<const float4*>(x + a2 + (XO));                     \
        V3 = *reinterpret_cast<const float4*>(x + a3 + (XO));                     \
    } while (0)

    float4 v0, v1, v2, v3, u0, u1, u2, u3;

    LOADX(v0, v1, v2, v3, 0);                       // batch 0
    LOADX(u0, u1, u2, u3, 1048576);                 // batch 1 (in flight)
    EPILOGUE(v0, v1, v2, v3, outb0);
    LOADX(v0, v1, v2, v3, 2097152);                 // batch 2 (in flight)
    EPILOGUE(u0, u1, u2, u3, outb0 + 1049600);
    LOADX(u0, u1, u2, u3, 3145728);                 // batch 3 (in flight)
    EPILOGUE(v0, v1, v2, v3, outb0 + 2099200);
    EPILOGUE(u0, u1, u2, u3, outb0 + 3148800);

#undef EPILOGUE
#undef LOADX
}

extern "C" void kernel_launch(void* const* d_in, const int* in_sizes, int n_in,
                              void* d_out, int out_size)
{
    // Identify inputs by size (defensive against ordering):
    //   x: 64*4*512*512 = 67108864, cls: 1024, pos: 1025*1024 = 1049600
    const float* x   = nullptr;
    const float* cls = nullptr;
    const float* pos = nullptr;
    for (int i = 0; i < n_in; i++) {
        if (in_sizes[i] == 67108864)     x   = (const float*)d_in[i];
        else if (in_sizes[i] == 1024)    cls = (const float*)d_in[i];
        else if (in_sizes[i] == 1049600) pos = (const float*)d_in[i];
    }
    float* out = (float*)d_out;

    dim3 grid(32, 8, 16);   // p-tiles, d-tiles, batch-groups of 4
    hilbert_main_kernel<<<grid, 256>>>(x, cls, pos, out);
}

// round 9
// speedup vs baseline: 1.0213x; 1.0213x over previous
#include <cuda_runtime.h>
#include <cuda_bf16.h>

// out[b, 1+d, p] = x[b, c, hx(p)*16+pi, hy(p)*16+pj] + pos[1+d, p]
//   where d = c*256 + pi*16 + pj, (hx,hy) = hilbert_d2xy(32, p)
// out[b, 0, e]   = cls[e] + pos[0, e]
//
// R5 smem-free register transpose + 2-batch pos amortization with explicit
// v/u double buffering: all 8 x-LDG.128s (batch b0 and b0+1) are in flight
// before any epilogue consumes (MLP 8 sustained). pos tile in registers,
// loaded once per CTA. Every STG.128 covers a full 128B line per 8-lane
// group. Grid 32x8x32 trims wave-quantization tail vs 1-batch CTAs.

__global__ __launch_bounds__(256) void hilbert_main_kernel(
    const float* __restrict__ x,
    const float* __restrict__ cls,
    const float* __restrict__ pos,
    float* __restrict__ out)
{
    const int tid = threadIdx.x;
    const int w   = tid >> 5;          // warp 0..7  -> d-quads 4w..4w+3
    const int l   = tid & 31;

    const int ptile = blockIdx.x;      // 0..31
    const int dtile = blockIdx.y;      // 0..7
    const int zb    = blockIdx.z;      // 0..31 -> batches 2zb, 2zb+1

    const int c   = dtile >> 1;        // channel
    const int pi0 = (dtile & 1) * 8;   // starting patch row within channel
    const int p0  = ptile * 32;
    const int d0  = dtile * 128;
    const int b0  = zb * 2;

    // Per-lane Hilbert base for patch p0+l (batch-independent part)
    int pbc;
    {
        int t = p0 + l;
        int hx = 0, hy = 0;
        #pragma unroll
        for (int s = 1; s < 32; s <<= 1) {
            int rx = 1 & (t >> 1);
            int ry = 1 & (t ^ rx);
            if (ry == 0) {
                if (rx == 1) { hx = s - 1 - hx; hy = s - 1 - hy; }
                int tmp = hx; hx = hy; hy = tmp;
            }
            hx += s * rx;
            hy += s * ry;
            t >>= 2;
        }
        pbc = (c * 512 + hx * 16 + pi0) * 512 + hy * 16;
    }

    const int q = l & 7;               // p-quad: patches 4q..4q+3
    const int s = l >> 3;              // sub-row selector
    const int srcoff = w * 512 + s * 4 + b0 * 1048576;

    const int a0 = __shfl_sync(0xffffffffu, pbc, 4 * q + 0) + srcoff;
    const int a1 = __shfl_sync(0xffffffffu, pbc, 4 * q + 1) + srcoff;
    const int a2 = __shfl_sync(0xffffffffu, pbc, 4 * q + 2) + srcoff;
    const int a3 = __shfl_sync(0xffffffffu, pbc, 4 * q + 3) + srcoff;

    // All 8 x loads (both batches) in flight before any consumption
    const float4 v0 = *reinterpret_cast<const float4*>(x + a0);
    const float4 v1 = *reinterpret_cast<const float4*>(x + a1);
    const float4 v2 = *reinterpret_cast<const float4*>(x + a2);
    const float4 v3 = *reinterpret_cast<const float4*>(x + a3);
    const float4 u0 = *reinterpret_cast<const float4*>(x + a0 + 1048576);
    const float4 u1 = *reinterpret_cast<const float4*>(x + a1 + 1048576);
    const float4 u2 = *reinterpret_cast<const float4*>(x + a2 + 1048576);
    const float4 u3 = *reinterpret_cast<const float4*>(x + a3 + 1048576);

    // Output rows 1 + d0 + 16w + 4s + j, cols p0 + 4q .. +3
    const int prow  = (1 + d0 + 16 * w + 4 * s) * 1024 + (p0 + 4 * q);
    const int outb0 = b0 * (1025 * 1024) + prow;

    // pos tile: loaded ONCE, reused for both batches
    const float4 pe0 = *reinterpret_cast<const float4*>(pos + prow);
    const float4 pe1 = *reinterpret_cast<const float4*>(pos + prow + 1024);
    const float4 pe2 = *reinterpret_cast<const float4*>(pos + prow + 2048);
    const float4 pe3 = *reinterpret_cast<const float4*>(pos + prow + 3072);

    // Fused row0 for both batches: out[b, 0, :] = cls + pos[0, :]
    if (ptile == 0 && dtile == 0) {
        float4 cv = *reinterpret_cast<const float4*>(cls + tid * 4);
        float4 pv = *reinterpret_cast<const float4*>(pos + tid * 4);
        cv.x += pv.x; cv.y += pv.y; cv.z += pv.z; cv.w += pv.w;
        *reinterpret_cast<float4*>(out + b0 * (1025 * 1024) + tid * 4) = cv;
        *reinterpret_cast<float4*>(out + (b0 + 1) * (1025 * 1024) + tid * 4) = cv;
    }

    float4 r;
    // ---- Batch b0 epilogue ----
    r = make_float4(v0.x + pe0.x, v1.x + pe0.y, v2.x + pe0.z, v3.x + pe0.w);
    __stcs(reinterpret_cast<float4*>(out + outb0), r);
    r = make_float4(v0.y + pe1.x, v1.y + pe1.y, v2.y + pe1.z, v3.y + pe1.w);
    __stcs(reinterpret_cast<float4*>(out + outb0 + 1024), r);
    r = make_float4(v0.z + pe2.x, v1.z + pe2.y, v2.z + pe2.z, v3.z + pe2.w);
    __stcs(reinterpret_cast<float4*>(out + outb0 + 2048), r);
    r = make_float4(v0.w + pe3.x, v1.w + pe3.y, v2.w + pe3.z, v3.w + pe3.w);
    __stcs(reinterpret_cast<float4*>(out + outb0 + 3072), r);

    // ---- Batch b0+1 epilogue ----
    const int outb1 = outb0 + 1025 * 1024;
    r = make_float4(u0.x + pe0.x, u1.x + pe0.y, u2.x + pe0.z, u3.x + pe0.w);
    __stcs(reinterpret_cast<float4*>(out + outb1), r);
    r = make_float4(u0.y + pe1.x, u1.y + pe1.y, u2.y + pe1.z, u3.y + pe1.w);
    __stcs(reinterpret_cast<float4*>(out + outb1 + 1024), r);
    r = make_float4(u0.z + pe2.x, u1.z + pe2.y, u2.z + pe2.z, u3.z + pe2.w);
    __stcs(reinterpret_cast<float4*>(out + outb1 + 2048), r);
    r = make_float4(u0.w + pe3.x, u1.w + pe3.y, u2.w + pe3.z, u3.w + pe3.w);
    __stcs(reinterpret_cast<float4*>(out + outb1 + 3072), r);
}

extern "C" void kernel_launch(void* const* d_in, const int* in_sizes, int n_in,
                              void* d_out, int out_size)
{
    // Identify inputs by size (defensive against ordering):
    //   x: 64*4*512*512 = 67108864, cls: 1024, pos: 1025*1024 = 1049600
    const float* x   = nullptr;
    const float* cls = nullptr;
    const float* pos = nullptr;
    for (int i = 0; i < n_in; i++) {
        if (in_sizes[i] == 67108864)     x   = (const float*)d_in[i];
        else if (in_sizes[i] == 1024)    cls = (const float*)d_in[i];
        else if (in_sizes[i] == 1049600) pos = (const float*)d_in[i];
    }
    float* out = (float*)d_out;

    dim3 grid(32, 8, 32);   // p-tiles, d-tiles, batch-pairs
    hilbert_main_kernel<<<grid, 256>>>(x, cls, pos, out);
}

// round 10
// speedup vs baseline: 1.0293x; 1.0078x over previous
#include <cuda_runtime.h>
#include <cuda_bf16.h>

// out[b, 1+d, p] = x[b, c, hx(p)*16+pi, hy(p)*16+pj] + pos[1+d, p]
//   where d = c*256 + pi*16 + pj, (hx,hy) = hilbert_d2xy(32, p)
// out[b, 0, e]   = cls[e] + pos[0, e]   (fused into ptile==0,dtile==0 CTA)
//
// Final form (R5 structure, lean addressing): smem-free 4x4 register
// transpose. 8-lane groups read 64B-contiguous patch rows (full sectors,
// MLP-4 batched); 4 pos loads batched before any store; every STG.128
// writes a full 128B output line per 8-lane group. All offsets are
// precomputed 32-bit ints (all tensors < 2^31 elements), so the epilogue
// is pure LDG/FADD/STG with immediate offsets.

__global__ __launch_bounds__(256) void hilbert_main_kernel(
    const float* __restrict__ x,
    const float* __restrict__ cls,
    const float* __restrict__ pos,
    float* __restrict__ out)
{
    const int tid = threadIdx.x;
    const int w   = tid >> 5;          // warp 0..7  -> d-quads 4w..4w+3
    const int l   = tid & 31;

    const int ptile = blockIdx.x;      // 0..31
    const int dtile = blockIdx.y;      // 0..7
    const int b     = blockIdx.z;      // 0..63

    const int c   = dtile >> 1;        // channel
    const int pi0 = (dtile & 1) * 8;   // starting patch row within channel
    const int p0  = ptile * 32;
    const int d0  = dtile * 128;
    const int out_b = b * (1025 * 1024);

    // Per-lane Hilbert d2xy for patch p0+l (N=32, 5 iterations)
    int pb;
    {
        int t = p0 + l;
        int hx = 0, hy = 0;
        #pragma unroll
        for (int s = 1; s < 32; s <<= 1) {
            int rx = 1 & (t >> 1);
            int ry = 1 & (t ^ rx);
            if (ry == 0) {
                if (rx == 1) { hx = s - 1 - hx; hy = s - 1 - hy; }
                int tmp = hx; hx = hy; hy = tmp;
            }
            hx += s * rx;
            hy += s * ry;
            t >>= 2;
        }
        pb = ((b * 4 + c) * 512 + hx * 16 + pi0) * 512 + hy * 16;
    }

    // Fused row0: out[b, 0, :] = cls + pos[0, :]  (one CTA per batch)
    if (ptile == 0 && dtile == 0) {
        float4 cv = *reinterpret_cast<const float4*>(cls + tid * 4);
        float4 pv = *reinterpret_cast<const float4*>(pos + tid * 4);
        cv.x += pv.x; cv.y += pv.y; cv.z += pv.z; cv.w += pv.w;
        *reinterpret_cast<float4*>(out + out_b + tid * 4) = cv;
    }

    const int q = l & 7;               // p-quad: patches 4q..4q+3
    const int s = l >> 3;              // sub-row selector
    // f = 4w + s : float4 slot within patch slab; d = 4f + j
    const int srcoff = w * 512 + s * 4;

    const int a0 = __shfl_sync(0xffffffffu, pb, 4 * q + 0) + srcoff;
    const int a1 = __shfl_sync(0xffffffffu, pb, 4 * q + 1) + srcoff;
    const int a2 = __shfl_sync(0xffffffffu, pb, 4 * q + 2) + srcoff;
    const int a3 = __shfl_sync(0xffffffffu, pb, 4 * q + 3) + srcoff;

    // All 4 x loads in flight before any consumption (MLP 4)
    const float4 v0 = *reinterpret_cast<const float4*>(x + a0);
    const float4 v1 = *reinterpret_cast<const float4*>(x + a1);
    const float4 v2 = *reinterpret_cast<const float4*>(x + a2);
    const float4 v3 = *reinterpret_cast<const float4*>(x + a3);

    // Output rows 1 + d0 + 16w + 4s + j, cols p0 + 4q .. +3
    const int prow   = (1 + d0 + 16 * w + 4 * s) * 1024 + (p0 + 4 * q);
    const int outoff = out_b + prow;

    // 4 pos loads batched (L2-resident) before any store
    const float4 pe0 = *reinterpret_cast<const float4*>(pos + prow);
    const float4 pe1 = *reinterpret_cast<const float4*>(pos + prow + 1024);
    const float4 pe2 = *reinterpret_cast<const float4*>(pos + prow + 2048);
    const float4 pe3 = *reinterpret_cast<const float4*>(pos + prow + 3072);

    float4 r;
    r = make_float4(v0.x + pe0.x, v1.x + pe0.y, v2.x + pe0.z, v3.x + pe0.w);
    __stcs(reinterpret_cast<float4*>(out + outoff), r);
    r = make_float4(v0.y + pe1.x, v1.y + pe1.y, v2.y + pe1.z, v3.y + pe1.w);
    __stcs(reinterpret_cast<float4*>(out + outoff + 1024), r);
    r = make_float4(v0.z + pe2.x, v1.z + pe2.y, v2.z + pe2.z, v3.z + pe2.w);
    __stcs(reinterpret_cast<float4*>(out + outoff + 2048), r);
    r = make_float4(v0.w + pe3.x, v1.w + pe3.y, v2.w + pe3.z, v3.w + pe3.w);
    __stcs(reinterpret_cast<float4*>(out + outoff + 3072), r);
}

extern "C" void kernel_launch(void* const* d_in, const int* in_sizes, int n_in,
                              void* d_out, int out_size)
{
    // Identify inputs by size (defensive against ordering):
    //   x: 64*4*512*512 = 67108864, cls: 1024, pos: 1025*1024 = 1049600
    const float* x   = nullptr;
    const float* cls = nullptr;
    const float* pos = nullptr;
    for (int i = 0; i < n_in; i++) {
        if (in_sizes[i] == 67108864)     x   = (const float*)d_in[i];
        else if (in_sizes[i] == 1024)    cls = (const float*)d_in[i];
        else if (in_sizes[i] == 1049600) pos = (const float*)d_in[i];
    }
    float* out = (float*)d_out;

    dim3 grid(32, 8, 64);   // p-tiles, d-tiles, batch
    hilbert_main_kernel<<<grid, 256>>>(x, cls, pos, out);
}